// round 1
// baseline (speedup 1.0000x reference)
#include <cuda_runtime.h>
#include <math.h>

// Problem constants (fixed by the dataset)
#define BSZ      32768
#define HD       128
#define G4       512          // 4*H gate rows
#define TIN      20
#define TDEC     45
#define NIN      2
#define NOUT     2

// Tiling
#define MB       32           // batch rows per CTA
#define NTHREADS 512
#define KC       32           // k-chunk of streamed weights
#define MT       4            // m-rows per thread
// per-thread tile: MT (m) x 2 (j) x 4 gates = 32 accumulators
// thread map: jg = tid & 63 (j0 = 2*jg), mg = tid >> 6 (m0 = 4*mg)

struct Smem {
    float h0s[MB][HD];        // layer0 h state, m-major
    float xh1[MB][2 * HD];    // [ y0 | h1 ] stacked along k, m-major
    float wch[KC][G4];        // streamed weight chunk, [k][gate-row]
    float be0[G4], be1[G4], bd0[G4], bd1[G4];   // combined biases
    float wie[G4][NIN];       // enc_Wih0
    float wid[G4][NIN];       // dec_Wih0
    float fcw[NOUT][HD];
    float fcb[NOUT];
    float xdec[MB][NIN];      // decoder feedback input
};

__device__ __forceinline__ float sigf(float x) {
    return 1.0f / (1.0f + __expf(-x));
}
__device__ __forceinline__ float tanhf_(float x) {
    return 2.0f / (1.0f + __expf(-2.0f * x)) - 1.0f;
}

// gates[g][m][j] += st[m][:] . W[g*128+j][:]   (W streamed through smem in KC chunks)
// st is m-major with row length KTOT. W0 covers k in [0,128), W1 covers k in [128,256).
template <int KTOT>
__device__ __forceinline__ void mm_acc(float acc[4][MT][2],
                                       const float* __restrict__ st,
                                       const float* __restrict__ W0,
                                       const float* __restrict__ W1,
                                       Smem* s, int tid, int m0, int j0)
{
    for (int kb = 0; kb < KTOT; kb += KC) {
        __syncthreads();  // protect wch reuse (prev chunk / prev matmul consumers done)
        const float* Wsrc = (kb < HD) ? (W0 + tid * HD + kb)
                                      : (W1 + tid * HD + (kb - HD));
        // thread == gate-row: coalesced-enough global read, conflict-free transposed store
        #pragma unroll
        for (int kk = 0; kk < KC; kk += 4) {
            float4 v = *(const float4*)(Wsrc + kk);
            s->wch[kk + 0][tid] = v.x;
            s->wch[kk + 1][tid] = v.y;
            s->wch[kk + 2][tid] = v.z;
            s->wch[kk + 3][tid] = v.w;
        }
        __syncthreads();
        #pragma unroll 8
        for (int kk = 0; kk < KC; kk++) {
            const int k = kb + kk;
            float hm[MT];
            #pragma unroll
            for (int m = 0; m < MT; m++)
                hm[m] = st[(m0 + m) * KTOT + k];   // warp-broadcast LDS
            #pragma unroll
            for (int g = 0; g < 4; g++) {
                float2 wv = *(const float2*)(&s->wch[kk][g * HD + j0]);
                #pragma unroll
                for (int m = 0; m < MT; m++) {
                    acc[g][m][0] = fmaf(hm[m], wv.x, acc[g][m][0]);
                    acc[g][m][1] = fmaf(hm[m], wv.y, acc[g][m][1]);
                }
            }
        }
    }
}

__global__ void __launch_bounds__(NTHREADS, 1)
trajectory_lstm_kernel(const float* __restrict__ inseq,
                       const float* __restrict__ eWih0, const float* __restrict__ eWhh0,
                       const float* __restrict__ ebih0, const float* __restrict__ ebhh0,
                       const float* __restrict__ eWih1, const float* __restrict__ eWhh1,
                       const float* __restrict__ ebih1, const float* __restrict__ ebhh1,
                       const float* __restrict__ dWih0, const float* __restrict__ dWhh0,
                       const float* __restrict__ dbih0, const float* __restrict__ dbhh0,
                       const float* __restrict__ dWih1, const float* __restrict__ dWhh1,
                       const float* __restrict__ dbih1, const float* __restrict__ dbhh1,
                       const float* __restrict__ fcW, const float* __restrict__ fcb,
                       float* __restrict__ out)
{
    extern __shared__ char raw[];
    Smem* s = (Smem*)raw;

    const int tid = threadIdx.x;
    const int bm  = blockIdx.x * MB;
    const int jg  = tid & 63;
    const int mg  = tid >> 6;
    const int j0  = jg * 2;
    const int m0  = mg * 4;

    // ---- one-time init ----
    {
        const int g = tid;                 // NTHREADS == G4
        s->be0[g] = ebih0[g] + ebhh0[g];
        s->be1[g] = ebih1[g] + ebhh1[g];
        s->bd0[g] = dbih0[g] + dbhh0[g];
        s->bd1[g] = dbih1[g] + dbhh1[g];
        s->wie[g][0] = eWih0[g * NIN + 0];
        s->wie[g][1] = eWih0[g * NIN + 1];
        s->wid[g][0] = dWih0[g * NIN + 0];
        s->wid[g][1] = dWih0[g * NIN + 1];
    }
    if (tid < NOUT * HD) s->fcw[tid >> 7][tid & 127] = fcW[tid];
    if (tid < NOUT)      s->fcb[tid] = fcb[tid];
    for (int i = tid; i < MB * HD; i += NTHREADS)     ((float*)s->h0s)[i] = 0.0f;
    for (int i = tid; i < MB * 2 * HD; i += NTHREADS) ((float*)s->xh1)[i] = 0.0f;
    if (tid < MB * NIN) {
        const int m = tid >> 1, c = tid & 1;
        s->xdec[m][c] = inseq[(size_t)(bm + m) * (TIN * NIN) + (TIN - 1) * NIN + c];
    }
    __syncthreads();

    float c0[MT][2] = {};
    float c1[MT][2] = {};
    float acc[4][MT][2];

    // ================= ENCODER =================
    for (int t = 0; t < TIN; t++) {
        // --- layer 0 ---
        float xr[MT][2];
        #pragma unroll
        for (int m = 0; m < MT; m++) {
            const float* p = inseq + (size_t)(bm + m0 + m) * (TIN * NIN) + t * NIN;
            xr[m][0] = p[0];
            xr[m][1] = p[1];
        }
        #pragma unroll
        for (int g = 0; g < 4; g++)
            #pragma unroll
            for (int jj = 0; jj < 2; jj++) {
                const int row = g * HD + j0 + jj;
                const float bb = s->be0[row];
                const float w0 = s->wie[row][0], w1 = s->wie[row][1];
                #pragma unroll
                for (int m = 0; m < MT; m++)
                    acc[g][m][jj] = fmaf(xr[m][1], w1, fmaf(xr[m][0], w0, bb));
            }
        mm_acc<HD>(acc, &s->h0s[0][0], eWhh0, nullptr, s, tid, m0, j0);
        __syncthreads();
        #pragma unroll
        for (int m = 0; m < MT; m++)
            #pragma unroll
            for (int jj = 0; jj < 2; jj++) {
                float ig = sigf(acc[0][m][jj]);
                float fg = sigf(acc[1][m][jj]);
                float gg = tanhf_(acc[2][m][jj]);
                float og = sigf(acc[3][m][jj]);
                float c = fmaf(fg, c0[m][jj], ig * gg);
                c0[m][jj] = c;
                float h = og * tanhf_(c);
                s->h0s[m0 + m][j0 + jj] = h;
                s->xh1[m0 + m][j0 + jj] = h;
            }
        // --- layer 1 (K=256 over [y0 | h1]) ---
        #pragma unroll
        for (int g = 0; g < 4; g++)
            #pragma unroll
            for (int jj = 0; jj < 2; jj++) {
                const float bb = s->be1[g * HD + j0 + jj];
                #pragma unroll
                for (int m = 0; m < MT; m++) acc[g][m][jj] = bb;
            }
        mm_acc<2 * HD>(acc, &s->xh1[0][0], eWih1, eWhh1, s, tid, m0, j0);
        __syncthreads();
        #pragma unroll
        for (int m = 0; m < MT; m++)
            #pragma unroll
            for (int jj = 0; jj < 2; jj++) {
                float ig = sigf(acc[0][m][jj]);
                float fg = sigf(acc[1][m][jj]);
                float gg = tanhf_(acc[2][m][jj]);
                float og = sigf(acc[3][m][jj]);
                float c = fmaf(fg, c1[m][jj], ig * gg);
                c1[m][jj] = c;
                s->xh1[m0 + m][HD + j0 + jj] = og * tanhf_(c);
            }
        // next mm_acc begins with __syncthreads -> xh1 writes are safe
    }

    // ================= DECODER =================
    for (int t = 0; t < TDEC; t++) {
        // --- layer 0 (input = previous prediction) ---
        float xr[MT][2];
        #pragma unroll
        for (int m = 0; m < MT; m++) {
            xr[m][0] = s->xdec[m0 + m][0];
            xr[m][1] = s->xdec[m0 + m][1];
        }
        #pragma unroll
        for (int g = 0; g < 4; g++)
            #pragma unroll
            for (int jj = 0; jj < 2; jj++) {
                const int row = g * HD + j0 + jj;
                const float bb = s->bd0[row];
                const float w0 = s->wid[row][0], w1 = s->wid[row][1];
                #pragma unroll
                for (int m = 0; m < MT; m++)
                    acc[g][m][jj] = fmaf(xr[m][1], w1, fmaf(xr[m][0], w0, bb));
            }
        mm_acc<HD>(acc, &s->h0s[0][0], dWhh0, nullptr, s, tid, m0, j0);
        __syncthreads();
        #pragma unroll
        for (int m = 0; m < MT; m++)
            #pragma unroll
            for (int jj = 0; jj < 2; jj++) {
                float ig = sigf(acc[0][m][jj]);
                float fg = sigf(acc[1][m][jj]);
                float gg = tanhf_(acc[2][m][jj]);
                float og = sigf(acc[3][m][jj]);
                float c = fmaf(fg, c0[m][jj], ig * gg);
                c0[m][jj] = c;
                float h = og * tanhf_(c);
                s->h0s[m0 + m][j0 + jj] = h;
                s->xh1[m0 + m][j0 + jj] = h;
            }
        // --- layer 1 ---
        #pragma unroll
        for (int g = 0; g < 4; g++)
            #pragma unroll
            for (int jj = 0; jj < 2; jj++) {
                const float bb = s->bd1[g * HD + j0 + jj];
                #pragma unroll
                for (int m = 0; m < MT; m++) acc[g][m][jj] = bb;
            }
        mm_acc<2 * HD>(acc, &s->xh1[0][0], dWih1, dWhh1, s, tid, m0, j0);
        __syncthreads();
        #pragma unroll
        for (int m = 0; m < MT; m++)
            #pragma unroll
            for (int jj = 0; jj < 2; jj++) {
                float ig = sigf(acc[0][m][jj]);
                float fg = sigf(acc[1][m][jj]);
                float gg = tanhf_(acc[2][m][jj]);
                float og = sigf(acc[3][m][jj]);
                float c = fmaf(fg, c1[m][jj], ig * gg);
                c1[m][jj] = c;
                s->xh1[m0 + m][HD + j0 + jj] = og * tanhf_(c);
            }
        __syncthreads();   // h1 complete before fc reads it
        // --- fc head: pred = h1 @ fcW^T + fcb ; also feeds next step ---
        if (tid < MB * NOUT) {
            const int m = tid >> 1, o = tid & 1;
            float a = s->fcb[o];
            #pragma unroll 8
            for (int j = 0; j < HD; j++)
                a = fmaf(s->xh1[m][HD + j], s->fcw[o][j], a);
            out[(size_t)(bm + m) * (TDEC * NOUT) + t * NOUT + o] = a;
            s->xdec[m][o] = a;
        }
        __syncthreads();   // xdec ready for next iteration
    }
}

extern "C" void kernel_launch(void* const* d_in, const int* in_sizes, int n_in,
                              void* d_out, int out_size)
{
    (void)in_sizes; (void)n_in; (void)out_size;
    const float* inseq = (const float*)d_in[0];
    const float* eWih0 = (const float*)d_in[1];
    const float* eWhh0 = (const float*)d_in[2];
    const float* ebih0 = (const float*)d_in[3];
    const float* ebhh0 = (const float*)d_in[4];
    const float* eWih1 = (const float*)d_in[5];
    const float* eWhh1 = (const float*)d_in[6];
    const float* ebih1 = (const float*)d_in[7];
    const float* ebhh1 = (const float*)d_in[8];
    const float* dWih0 = (const float*)d_in[9];
    const float* dWhh0 = (const float*)d_in[10];
    const float* dbih0 = (const float*)d_in[11];
    const float* dbhh0 = (const float*)d_in[12];
    const float* dWih1 = (const float*)d_in[13];
    const float* dWhh1 = (const float*)d_in[14];
    const float* dbih1 = (const float*)d_in[15];
    const float* dbhh1 = (const float*)d_in[16];
    const float* fcW   = (const float*)d_in[17];
    const float* fcb   = (const float*)d_in[18];
    float* out = (float*)d_out;

    cudaFuncSetAttribute(trajectory_lstm_kernel,
                         cudaFuncAttributeMaxDynamicSharedMemorySize,
                         (int)sizeof(Smem));

    trajectory_lstm_kernel<<<BSZ / MB, NTHREADS, sizeof(Smem)>>>(
        inseq,
        eWih0, eWhh0, ebih0, ebhh0,
        eWih1, eWhh1, ebih1, ebhh1,
        dWih0, dWhh0, dbih0, dbhh0,
        dWih1, dWhh1, dbih1, dbhh1,
        fcW, fcb, out);
}

// round 2
// speedup vs baseline: 1.8073x; 1.8073x over previous
#include <cuda_runtime.h>

// Problem constants
#define BSZ 32768
#define HD  128
#define G4  512
#define TIN 20
#define TDEC 45
#define NIN 2
#define NOUT 2

// Tiling
#define MB 32            // batch rows per CTA
#define NTHREADS 512
#define KC 32            // k-chunk
#define P0 132           // padded row stride for h0 state (mult of 4, stride%32=4)
#define P1 260           // padded row stride for [y0|h1] state

typedef unsigned long long ull;

struct Smem {
    float wch[2][KC][G4];        // double-buffered transposed weight chunk (XOR-swizzled cols)
    float h0s[MB * P0];          // layer0 h state
    float xh1[MB * P1];          // [ y0 (0..127) | h1 (128..255) ]
    float xin[MB * (TIN * NIN)]; // encoder inputs staged once
    float be0[G4], be1[G4], bd0[G4], bd1[G4];
    float wieT[2][G4], widT[2][G4];   // input weights transposed for packed loads
    float fcw[NOUT][HD];
    float fcb[NOUT];
    float xdec[MB][NOUT];
};

__device__ __forceinline__ ull pack2(float x) {
    ull r; asm("mov.b64 %0, {%1, %1};" : "=l"(r) : "f"(x)); return r;
}
__device__ __forceinline__ float2 unpk(ull v) {
    float lo, hi; asm("mov.b64 {%0, %1}, %2;" : "=f"(lo), "=f"(hi) : "l"(v));
    return make_float2(lo, hi);
}
#define FMA2(d, a, b) asm("fma.rn.f32x2 %0, %1, %2, %0;" : "+l"(d) : "l"(a), "l"(b))

__device__ __forceinline__ float sigf(float x) {
    return __fdividef(1.0f, 1.0f + __expf(-x));
}
__device__ __forceinline__ float tanhf_(float x) {
    return 2.0f * __fdividef(1.0f, 1.0f + __expf(-2.0f * x)) - 1.0f;
}

// ---- weight staging: coalesced LDG (32 rows x 128B per warp) ----
__device__ __forceinline__ void stage_ldg(float4 stg[8], const float* __restrict__ W,
                                          int w, int l) {
    const int b = l & 7, r = l >> 3;
    #pragma unroll
    for (int i = 0; i < 8; i++)
        stg[i] = *(const float4*)(W + ((w << 5) + (i << 2) + r) * HD + (b << 2));
}
// transpose-store with XOR swizzle: wch[kk][col ^ (kk & 28)], kk = 4b+c
// STS banks: (l>>3) ^ (b<<2) -> 32 distinct -> conflict-free
__device__ __forceinline__ void stage_sts(float* buf, const float4 stg[8], int w, int l) {
    const int b = l & 7, r = l >> 3;
    float* d0 = buf + (b << 2) * G4;
    #pragma unroll
    for (int i = 0; i < 8; i++) {
        const int col = (((w << 5) + (i << 2) + r)) ^ (b << 2);
        d0[col]          = stg[i].x;
        d0[col + G4]     = stg[i].y;
        d0[col + 2 * G4] = stg[i].z;
        d0[col + 3 * G4] = stg[i].w;
    }
}

// gates += st[m][:] . W^T, packed-f32x2 over j pairs.
// W0 covers k in [0,128), W1 covers [128,256).
template <int KTOT, int P>
__device__ __forceinline__ void matmul(ull acc[4][2][2], const float* __restrict__ st,
                                       const float* __restrict__ W0,
                                       const float* __restrict__ W1,
                                       Smem* s, int w, int l, int m0, int j0)
{
    const int NCH = KTOT / KC;
    {   // stage chunk 0 into buffer 0
        float4 stg[8];
        stage_ldg(stg, W0, w, l);
        stage_sts(&s->wch[0][0][0], stg, w, l);
    }
    __syncthreads();
    #pragma unroll 1
    for (int c = 0; c < NCH; c++) {
        float4 stg[8];
        const bool more = (c + 1 < NCH);
        if (more) {
            const int kn = (c + 1) * KC;
            const float* W = (kn < HD) ? (W0 + kn) : (W1 + (kn - HD));
            stage_ldg(stg, W, w, l);           // issue early; latency hidden by compute
        }
        const float* wb  = &s->wch[c & 1][0][0];
        const float* hp0 = st + m0 * P + c * KC;
        const float* hp1 = hp0 + P;
        #pragma unroll 2
        for (int k4 = 0; k4 < KC; k4 += 4) {
            const float4 hA = *(const float4*)(hp0 + k4);
            const float4 hB = *(const float4*)(hp1 + k4);
            #pragma unroll
            for (int u = 0; u < 4; u++) {
                const int kk = k4 + u;
                const ull ha = pack2(((const float*)&hA)[u]);
                const ull hb = pack2(((const float*)&hB)[u]);
                const float* wr = wb + kk * G4;
                const int xk = kk & 28;
                #pragma unroll
                for (int g = 0; g < 4; g++) {
                    const ulonglong2 wv =
                        *(const ulonglong2*)(wr + ((g * HD + j0) ^ xk));
                    FMA2(acc[g][0][0], wv.x, ha);
                    FMA2(acc[g][0][1], wv.x, hb);
                    FMA2(acc[g][1][0], wv.y, ha);
                    FMA2(acc[g][1][1], wv.y, hb);
                }
            }
        }
        if (more) stage_sts(&s->wch[(c + 1) & 1][0][0], stg, w, l);
        __syncthreads();
    }
}

__device__ __forceinline__ void init_bias(ull acc[4][2][2], const float* bias, int j0) {
    #pragma unroll
    for (int g = 0; g < 4; g++)
        #pragma unroll
        for (int jp = 0; jp < 2; jp++) {
            const ull bv = *(const ull*)(bias + g * HD + j0 + jp * 2);
            acc[g][jp][0] = bv;
            acc[g][jp][1] = bv;
        }
}

__device__ __forceinline__ void add_xterm(ull acc[4][2][2], const float (*wT)[G4],
                                          float xA0, float xA1, float xB0, float xB1,
                                          int j0) {
    const ull a0 = pack2(xA0), a1 = pack2(xA1);
    const ull b0 = pack2(xB0), b1 = pack2(xB1);
    #pragma unroll
    for (int g = 0; g < 4; g++)
        #pragma unroll
        for (int jp = 0; jp < 2; jp++) {
            const ull w0 = *(const ull*)(&wT[0][g * HD + j0 + jp * 2]);
            const ull w1 = *(const ull*)(&wT[1][g * HD + j0 + jp * 2]);
            FMA2(acc[g][jp][0], w0, a0);
            FMA2(acc[g][jp][0], w1, a1);
            FMA2(acc[g][jp][1], w0, b0);
            FMA2(acc[g][jp][1], w1, b1);
        }
}

template <bool DUAL>
__device__ __forceinline__ void epilogue(ull acc[4][2][2], float cst[2][4],
                                         float* dst0, int p0, float* dst1, int p1,
                                         int m0, int j0) {
    #pragma unroll
    for (int mi = 0; mi < 2; mi++)
        #pragma unroll
        for (int jp = 0; jp < 2; jp++) {
            const float2 ai = unpk(acc[0][jp][mi]);
            const float2 af = unpk(acc[1][jp][mi]);
            const float2 ag = unpk(acc[2][jp][mi]);
            const float2 ao = unpk(acc[3][jp][mi]);
            #pragma unroll
            for (int q = 0; q < 2; q++) {
                const float xi = q ? ai.y : ai.x;
                const float xf = q ? af.y : af.x;
                const float xg = q ? ag.y : ag.x;
                const float xo = q ? ao.y : ao.x;
                float cn = fmaf(sigf(xf), cst[mi][jp * 2 + q], sigf(xi) * tanhf_(xg));
                cst[mi][jp * 2 + q] = cn;
                const float h = sigf(xo) * tanhf_(cn);
                dst0[(m0 + mi) * p0 + j0 + jp * 2 + q] = h;
                if (DUAL) dst1[(m0 + mi) * p1 + j0 + jp * 2 + q] = h;
            }
        }
}

__global__ void __launch_bounds__(NTHREADS, 1)
trajectory_lstm_kernel(const float* __restrict__ inseq,
                       const float* __restrict__ eWih0, const float* __restrict__ eWhh0,
                       const float* __restrict__ ebih0, const float* __restrict__ ebhh0,
                       const float* __restrict__ eWih1, const float* __restrict__ eWhh1,
                       const float* __restrict__ ebih1, const float* __restrict__ ebhh1,
                       const float* __restrict__ dWih0, const float* __restrict__ dWhh0,
                       const float* __restrict__ dbih0, const float* __restrict__ dbhh0,
                       const float* __restrict__ dWih1, const float* __restrict__ dWhh1,
                       const float* __restrict__ dbih1, const float* __restrict__ dbhh1,
                       const float* __restrict__ fcW, const float* __restrict__ fcb,
                       float* __restrict__ out)
{
    extern __shared__ char raw[];
    Smem* s = (Smem*)raw;

    const int tid = threadIdx.x;
    const int w = tid >> 5, l = tid & 31;
    const int wj = w & 3, wm = w >> 2;
    const int jl = l >> 2, ml = l & 3;
    const int j0 = wj * 32 + jl * 4;    // 4 consecutive j-columns per thread
    const int m0 = wm * 8 + ml * 2;     // 2 consecutive m-rows per thread
    const int bm = blockIdx.x * MB;

    // ---- one-time init ----
    {
        const int g = tid;  // NTHREADS == G4
        s->be0[g] = ebih0[g] + ebhh0[g];
        s->be1[g] = ebih1[g] + ebhh1[g];
        s->bd0[g] = dbih0[g] + dbhh0[g];
        s->bd1[g] = dbih1[g] + dbhh1[g];
        s->wieT[0][g] = eWih0[g * 2];
        s->wieT[1][g] = eWih0[g * 2 + 1];
        s->widT[0][g] = dWih0[g * 2];
        s->widT[1][g] = dWih0[g * 2 + 1];
    }
    if (tid < NOUT * HD) ((float*)s->fcw)[tid] = fcW[tid];
    if (tid < NOUT)      s->fcb[tid] = fcb[tid];
    for (int i = tid; i < MB * P0; i += NTHREADS) s->h0s[i] = 0.0f;
    for (int i = tid; i < MB * P1; i += NTHREADS) s->xh1[i] = 0.0f;
    for (int i = tid; i < MB * TIN * NIN; i += NTHREADS)
        s->xin[i] = inseq[(size_t)bm * (TIN * NIN) + i];
    if (tid < MB * NOUT) {
        const int m = tid >> 1, c = tid & 1;
        s->xdec[m][c] = inseq[(size_t)(bm + m) * (TIN * NIN) + (TIN - 1) * NIN + c];
    }
    __syncthreads();

    float c0[2][4] = {}, c1[2][4] = {};
    ull acc[4][2][2];

    // ================= ENCODER =================
    for (int t = 0; t < TIN; t++) {
        init_bias(acc, s->be0, j0);
        add_xterm(acc, s->wieT,
                  s->xin[m0 * (TIN * NIN) + 2 * t], s->xin[m0 * (TIN * NIN) + 2 * t + 1],
                  s->xin[(m0 + 1) * (TIN * NIN) + 2 * t],
                  s->xin[(m0 + 1) * (TIN * NIN) + 2 * t + 1], j0);
        matmul<HD, P0>(acc, s->h0s, eWhh0, eWhh0, s, w, l, m0, j0);
        epilogue<true>(acc, c0, s->h0s, P0, s->xh1, P1, m0, j0);

        init_bias(acc, s->be1, j0);
        matmul<2 * HD, P1>(acc, s->xh1, eWih1, eWhh1, s, w, l, m0, j0);
        epilogue<false>(acc, c1, s->xh1 + HD, P1, nullptr, 0, m0, j0);
    }

    // ================= DECODER =================
    for (int t = 0; t < TDEC; t++) {
        init_bias(acc, s->bd0, j0);
        add_xterm(acc, s->widT,
                  s->xdec[m0][0], s->xdec[m0][1],
                  s->xdec[m0 + 1][0], s->xdec[m0 + 1][1], j0);
        matmul<HD, P0>(acc, s->h0s, dWhh0, dWhh0, s, w, l, m0, j0);
        epilogue<true>(acc, c0, s->h0s, P0, s->xh1, P1, m0, j0);

        init_bias(acc, s->bd1, j0);
        matmul<2 * HD, P1>(acc, s->xh1, dWih1, dWhh1, s, w, l, m0, j0);
        epilogue<false>(acc, c1, s->xh1 + HD, P1, nullptr, 0, m0, j0);
        __syncthreads();   // h1 complete before fc reads it

        // fc head: pred = h1 @ fcW^T + fcb (parallel dot, 8-lane tree reduce)
        {
            const int m = tid >> 4, o = (tid >> 3) & 1, p = tid & 7;
            const float* hr = s->xh1 + m * P1 + HD + p * 16;
            const float* wr = s->fcw[o] + p * 16;
            float a = 0.0f;
            #pragma unroll
            for (int k = 0; k < 16; k++) a = fmaf(hr[k], wr[k], a);
            a += __shfl_down_sync(0xffffffffu, a, 4, 8);
            a += __shfl_down_sync(0xffffffffu, a, 2, 8);
            a += __shfl_down_sync(0xffffffffu, a, 1, 8);
            if (p == 0) {
                a += s->fcb[o];
                out[(size_t)(bm + m) * (TDEC * NOUT) + t * NOUT + o] = a;
                s->xdec[m][o] = a;
            }
        }
        __syncthreads();   // xdec ready for next step
    }
}

extern "C" void kernel_launch(void* const* d_in, const int* in_sizes, int n_in,
                              void* d_out, int out_size)
{
    (void)in_sizes; (void)n_in; (void)out_size;
    const float* inseq = (const float*)d_in[0];
    const float* eWih0 = (const float*)d_in[1];
    const float* eWhh0 = (const float*)d_in[2];
    const float* ebih0 = (const float*)d_in[3];
    const float* ebhh0 = (const float*)d_in[4];
    const float* eWih1 = (const float*)d_in[5];
    const float* eWhh1 = (const float*)d_in[6];
    const float* ebih1 = (const float*)d_in[7];
    const float* ebhh1 = (const float*)d_in[8];
    const float* dWih0 = (const float*)d_in[9];
    const float* dWhh0 = (const float*)d_in[10];
    const float* dbih0 = (const float*)d_in[11];
    const float* dbhh0 = (const float*)d_in[12];
    const float* dWih1 = (const float*)d_in[13];
    const float* dWhh1 = (const float*)d_in[14];
    const float* dbih1 = (const float*)d_in[15];
    const float* dbhh1 = (const float*)d_in[16];
    const float* fcW   = (const float*)d_in[17];
    const float* fcb   = (const float*)d_in[18];
    float* out = (float*)d_out;

    cudaFuncSetAttribute(trajectory_lstm_kernel,
                         cudaFuncAttributeMaxDynamicSharedMemorySize,
                         (int)sizeof(Smem));

    trajectory_lstm_kernel<<<BSZ / MB, NTHREADS, sizeof(Smem)>>>(
        inseq,
        eWih0, eWhh0, ebih0, ebhh0,
        eWih1, eWhh1, ebih1, ebhh1,
        dWih0, dWhh0, dbih0, dbhh0,
        dWih1, dWhh1, dbih1, dbhh1,
        fcW, fcb, out);
}